// round 17
// baseline (speedup 1.0000x reference)
#include <cuda_runtime.h>
#include <cuda_fp16.h>
#include <cstdint>

#define BB 8192
#define DD 256
#define TM 128
#define TN 64
#define NRB (BB/TM)          // 64 rowblocks
#define NCT (BB/TN)          // 128 col tiles
#define TOTW (NRB*NCT)       // 8192 tile visits
#define NCTA 148
#define WBASE (TOTW/NCTA)    // 55
#define WREM  (TOTW%NCTA)    // 52

static __device__ __align__(16) __half g_a16[BB*DD];
static __device__ __align__(16) __half g_p16[BB*DD];
static __device__ float    g_psum[BB];
static __device__ uint32_t g_pmaxu[BB];   // monotonic-mapped float
static __device__ float    g_diag[BB];
static __device__ unsigned long long g_done = 0ull;  // completion counter (monotonic)

// dynamic smem: A0 @0 (64KB), A1 @64KB, P0 @128KB (32KB), P1 @160KB, stats @192KB
#define SM_A0 0u
#define SM_A1 65536u
#define SM_P0 131072u
#define SM_P1 163840u
#define SM_ST 196608u
#define SMEM_BYTES (196608 + 8192)

#define INVT (1.0f/0.07f)
// exp((v-1)/T) = 2^(v*C1 - C1),  C1 = (1/T)*log2(e)
#define C1F 20.609929155556627f
#define NEGINF __int_as_float(0xff800000)

__device__ __forceinline__ uint32_t s2u(const void* p) {
    uint32_t r;
    asm("{ .reg .u64 t; cvta.to.shared.u64 t, %1; cvt.u32.u64 %0, t; }" : "=r"(r) : "l"(p));
    return r;
}
__device__ __forceinline__ uint32_t fmap(float x) {
    uint32_t u = __float_as_uint(x);
    return (u & 0x80000000u) ? ~u : (u | 0x80000000u);
}
__device__ __forceinline__ float funmap(uint32_t m) {
    uint32_t u = (m & 0x80000000u) ? (m & 0x7FFFFFFFu) : ~m;
    return __uint_as_float(u);
}

// A tile: 128 rows x 256 fp16 (64KB). 512 threads, 8 chunks of 16B each.
// Row stride 512B; chunk' = chunk ^ (row & 7) xor swizzle.
__device__ __forceinline__ void load_tileA(uint32_t s_dst, const __half* gtile, int tid) {
    const int row = tid >> 2;          // 0..127
    const int q   = tid & 3;
    const char* src = (const char*)(gtile + (size_t)row * DD) + q * 128;
    const uint32_t rbase = s_dst + (uint32_t)row * 512u;
    const uint32_t rx = (uint32_t)(row & 7);
    #pragma unroll
    for (int j = 0; j < 8; ++j) {
        uint32_t chunk = (uint32_t)(q * 8 + j);
        uint32_t d = rbase + ((chunk ^ rx) << 4);
        asm volatile("cp.async.cg.shared.global [%0], [%1], 16;"
                     :: "r"(d), "l"(src + j * 16));
    }
}
// Half of an A tile (rows half*64 .. half*64+63), 32KB, 4 chunks per thread.
__device__ __forceinline__ void load_tileA_half(uint32_t s_dst, const __half* gtile,
                                                int tid, int half) {
    const int row = half * 64 + (tid >> 3);
    const int q   = tid & 7;
    const char* src = (const char*)(gtile + (size_t)row * DD) + q * 64;
    const uint32_t rbase = s_dst + (uint32_t)row * 512u;
    const uint32_t rx = (uint32_t)(row & 7);
    #pragma unroll
    for (int j = 0; j < 4; ++j) {
        uint32_t chunk = (uint32_t)(q * 4 + j);
        uint32_t d = rbase + ((chunk ^ rx) << 4);
        asm volatile("cp.async.cg.shared.global [%0], [%1], 16;"
                     :: "r"(d), "l"(src + j * 16));
    }
}
// P tile: 64 rows x 256 fp16 (32KB). 512 threads, 4 chunks of 16B each.
__device__ __forceinline__ void load_tileP(uint32_t s_dst, const __half* gtile, int tid) {
    const int row = tid >> 3;
    const int q   = tid & 7;
    const char* src = (const char*)(gtile + (size_t)row * DD) + q * 64;
    const uint32_t rbase = s_dst + (uint32_t)row * 512u;
    const uint32_t rx = (uint32_t)(row & 7);
    #pragma unroll
    for (int j = 0; j < 4; ++j) {
        uint32_t chunk = (uint32_t)(q * 4 + j);
        uint32_t d = rbase + ((chunk ^ rx) << 4);
        asm volatile("cp.async.cg.shared.global [%0], [%1], 16;"
                     :: "r"(d), "l"(src + j * 16));
    }
}

#define LDSM_X4(r0, r1, r2, r3, addr) \
    asm volatile("ldmatrix.sync.aligned.m8n8.x4.shared.b16 {%0,%1,%2,%3}, [%4];" \
                 : "=r"(r0), "=r"(r1), "=r"(r2), "=r"(r3) : "r"(addr))

#define MMA16816H(c, a, b0v, b1v) \
    asm volatile("mma.sync.aligned.m16n8k16.row.col.f16.f16.f16.f16 " \
                 "{%0,%1}, {%2,%3,%4,%5}, {%6,%7}, {%0,%1};" \
                 : "+r"((c)[0]), "+r"((c)[1]) \
                 : "r"((a)[0]), "r"((a)[1]), "r"((a)[2]), "r"((a)[3]), \
                   "r"(b0v), "r"(b1v))

// Four rows per warp (MLP=8): L2-normalize fp32 -> fp16, reset stats.
__global__ void nrm_kernel(const float* __restrict__ a, const float* __restrict__ p) {
    const int lane = threadIdx.x & 31;
    const int w    = threadIdx.x >> 5;
    const int r0   = blockIdx.x * 64 + w * 4;
    const float* srcT = blockIdx.y ? p : a;
    __half* dstT = blockIdx.y ? g_p16 : g_a16;

    if (blockIdx.y == 0 && lane < 4) {
        const int row = r0 + lane;
        g_psum[row] = 0.f;
        g_pmaxu[row] = 0x007FFFFFu;   // fmap(-inf)
        g_diag[row] = 0.f;
    }

    float4 v[4][2];
    const float* s = srcT + (size_t)r0 * DD + lane * 8;
    #pragma unroll
    for (int r = 0; r < 4; ++r) {
        v[r][0] = *(const float4*)(s + r * DD);
        v[r][1] = *(const float4*)(s + r * DD + 4);
    }
    float ss[4];
    #pragma unroll
    for (int r = 0; r < 4; ++r)
        ss[r] = v[r][0].x*v[r][0].x + v[r][0].y*v[r][0].y + v[r][0].z*v[r][0].z + v[r][0].w*v[r][0].w
              + v[r][1].x*v[r][1].x + v[r][1].y*v[r][1].y + v[r][1].z*v[r][1].z + v[r][1].w*v[r][1].w;
    #pragma unroll
    for (int o = 16; o > 0; o >>= 1)
        #pragma unroll
        for (int r = 0; r < 4; ++r)
            ss[r] += __shfl_xor_sync(0xffffffffu, ss[r], o);

    __half* d = dstT + (size_t)r0 * DD + lane * 8;
    #pragma unroll
    for (int r = 0; r < 4; ++r) {
        float sc = 1.0f / fmaxf(sqrtf(ss[r]), 1e-12f);
        __half2 h[4];
        h[0] = __floats2half2_rn(v[r][0].x*sc, v[r][0].y*sc);
        h[1] = __floats2half2_rn(v[r][0].z*sc, v[r][0].w*sc);
        h[2] = __floats2half2_rn(v[r][1].x*sc, v[r][1].y*sc);
        h[3] = __floats2half2_rn(v[r][1].z*sc, v[r][1].w*sc);
        *(uint4*)(d + r * DD) = *(const uint4*)h;
    }
}

__global__ __launch_bounds__(512, 1) void fused_kernel(float* out) {
    extern __shared__ char smem[];
    const uint32_t sb = s2u(smem);
    const int tid = threadIdx.x;
    const int lane = tid & 31, wid = tid >> 5;
    const int warp_m = wid >> 1;          // 0..7 (16 rows each)
    const int warp_n = wid & 1;           // 0..1 (32 cols each)
    const int c = blockIdx.x;

    // balanced contiguous range of tile visits [start, start+len)
    const int start = WBASE * c + (c < WREM ? c : WREM);
    const int len   = WBASE + (c < WREM ? 1 : 0);
    const int rb0   = start >> 7;
    const int rbLast = (start + len - 1) >> 7;
    const bool has2 = (rbLast != rb0);
    const int seg1 = has2 ? ((rb0 + 1) * NCT - start) : len;
    const bool earlyA2 = has2 && (seg1 < 3);
    const int kA = (seg1 >= 6) ? (seg1 - 6) : 0;   // A-prefetch halves at kA, kA+1

    const uint32_t lrow  = (uint32_t)(lane & 15);
    const uint32_t khalf = (uint32_t)(lane >> 4);
    const uint32_t xorp  = (uint32_t)(lane & 7);
    const float NEG = NEGINF;
    const int rowLocal = warp_m*16 + (lane >> 2);  // + 8h

    float* sSum = (float*)(smem + SM_ST);        // [2][128]
    float* sMax = sSum + 256;
    float* sDg  = sMax + 256;

    // ---- prologue ----
    load_tileA(sb + SM_A0, g_a16 + (size_t)rb0 * TM * DD, tid);
    if (earlyA2)
        load_tileA(sb + SM_A1, g_a16 + (size_t)(rb0 + 1) * TM * DD, tid);
    load_tileP(sb + SM_P0, g_p16 + (size_t)(start & 127) * TN * DD, tid);
    asm volatile("cp.async.commit_group;");
    if (len > 1)
        load_tileP(sb + SM_P1, g_p16 + (size_t)((start + 1) & 127) * TN * DD, tid);
    asm volatile("cp.async.commit_group;");

    float sum[2], mx[2], dg[2];
    #pragma unroll
    for (int h = 0; h < 2; ++h) { sum[h]=0.f; mx[h]=NEG; dg[h]=0.f; }

    #pragma unroll 1
    for (int k = 0; k < len; ++k) {
        const int v  = start + k;
        const int rb = v >> 7;
        const int ct = v & 127;
        const int abuf = rb - rb0;             // 0 or 1

        if (k + 1 < len) asm volatile("cp.async.wait_group 1;");
        else             asm volatile("cp.async.wait_group 0;");
        __syncthreads();

        const uint32_t aB = sb + (abuf ? SM_A1 : SM_A0)
                          + (uint32_t)(warp_m*16 + (int)lrow) * 512u;
        const uint32_t pb = (k & 1) ? SM_P1 : SM_P0;
        uint32_t bBase[2];
        #pragma unroll
        for (int nfp = 0; nfp < 2; ++nfp)
            bBase[nfp] = sb + pb + (uint32_t)(warp_n*32 + nfp*16 + (int)lrow) * 512u;

        uint32_t acc[4][2];
        #pragma unroll
        for (int nf = 0; nf < 4; ++nf) { acc[nf][0] = 0u; acc[nf][1] = 0u; }

        #pragma unroll
        for (int ks = 0; ks < 16; ++ks) {
            const uint32_t coff = (((uint32_t)(2*ks) + khalf) ^ xorp) << 4;
            uint32_t a[4];
            LDSM_X4(a[0], a[1], a[2], a[3], aB + coff);
            uint32_t b[2][4];
            #pragma unroll
            for (int nfp = 0; nfp < 2; ++nfp)
                LDSM_X4(b[nfp][0], b[nfp][1], b[nfp][2], b[nfp][3], bBase[nfp] + coff);
            MMA16816H(acc[0], a, b[0][0], b[0][2]);
            MMA16816H(acc[1], a, b[0][1], b[0][3]);
            MMA16816H(acc[2], a, b[1][0], b[1][2]);
            MMA16816H(acc[3], a, b[1][1], b[1][3]);
        }

        __syncthreads();
        // refill ring for visit v+2 (ct wraps into the next rowblock's window naturally)
        if (k + 2 < len) {
            load_tileP(sb + pb, g_p16 + (size_t)((v + 2) & 127) * TN * DD, tid);
            if (!earlyA2 && has2) {
                if (k == kA)     load_tileA_half(sb + SM_A1, g_a16 + (size_t)(rb0+1)*TM*DD, tid, 0);
                if (k == kA + 1) load_tileA_half(sb + SM_A1, g_a16 + (size_t)(rb0+1)*TM*DD, tid, 1);
            }
            asm volatile("cp.async.commit_group;");
        } else {
            asm volatile("cp.async.commit_group;");   // keep group count in step
        }

        // Epilogue: fold 128x64 tile into streaming stats (registers only)
        if ((ct >> 1) != rb) {
            #pragma unroll
            for (int h = 0; h < 2; ++h) {
                float lsum = 0.f, lmx = mx[h];
                #pragma unroll
                for (int nf = 0; nf < 4; ++nf) {
                    float2 vv = __half22float2(*(__half2*)&acc[nf][h]);
                    float ex0, ex1;
                    asm("ex2.approx.f32 %0, %1;" : "=f"(ex0) : "f"(fmaf(vv.x, C1F, -C1F)));
                    asm("ex2.approx.f32 %0, %1;" : "=f"(ex1) : "f"(fmaf(vv.y, C1F, -C1F)));
                    lsum += ex0 + ex1;
                    lmx = fmaxf(lmx, fmaxf(vv.x, vv.y));
                }
                sum[h] += lsum;
                mx[h] = lmx;
            }
        } else {
            const int cb0 = ct*TN + warp_n*32 + (lane & 3)*2;
            #pragma unroll
            for (int h = 0; h < 2; ++h) {
                const int r = rb*TM + rowLocal + 8*h;
                float lsum = 0.f;
                #pragma unroll
                for (int nf = 0; nf < 4; ++nf) {
                    float2 vv = __half22float2(*(__half2*)&acc[nf][h]);
                    float ex0, ex1;
                    asm("ex2.approx.f32 %0, %1;" : "=f"(ex0) : "f"(fmaf(vv.x, C1F, -C1F)));
                    asm("ex2.approx.f32 %0, %1;" : "=f"(ex1) : "f"(fmaf(vv.y, C1F, -C1F)));
                    lsum += ex0 + ex1;
                    bool d0 = ((cb0 + nf*8    ) == r);
                    bool d1 = ((cb0 + nf*8 + 1) == r);
                    mx[h] = fmaxf(mx[h], d0 ? NEG : vv.x);
                    mx[h] = fmaxf(mx[h], d1 ? NEG : vv.y);
                    if (d0) dg[h] = vv.x;
                    if (d1) dg[h] = vv.y;
                }
                sum[h] += lsum;
            }
        }

        // flush stats at rowblock boundary / end
        const bool flush = (k == len - 1) || (((v + 1) >> 7) != rb);
        if (flush) {
            const int R0 = rb * TM;
            #pragma unroll
            for (int h = 0; h < 2; ++h) {
                #pragma unroll
                for (int o = 1; o < 4; o <<= 1) {
                    sum[h] += __shfl_xor_sync(0xffffffffu, sum[h], o);
                    mx[h]  = fmaxf(mx[h], __shfl_xor_sync(0xffffffffu, mx[h], o));
                    dg[h]  += __shfl_xor_sync(0xffffffffu, dg[h], o);
                }
            }
            if ((lane & 3) == 0) {
                #pragma unroll
                for (int h = 0; h < 2; ++h) {
                    int rl = rowLocal + 8*h;   // 0..127
                    sSum[warp_n*128 + rl] = sum[h];
                    sMax[warp_n*128 + rl] = mx[h];
                    sDg [warp_n*128 + rl] = dg[h];
                }
            }
            __syncthreads();
            if (tid < 128) {
                float S = sSum[tid] + sSum[128 + tid];
                float M = fmaxf(sMax[tid], sMax[128 + tid]);
                float D = sDg[tid] + sDg[128 + tid];
                atomicAdd(&g_psum[R0 + tid], S);
                atomicMax(&g_pmaxu[R0 + tid], fmap(M));
                if (D != 0.f) atomicAdd(&g_diag[R0 + tid], D);
            }
            __syncthreads();
            #pragma unroll
            for (int h = 0; h < 2; ++h) { sum[h]=0.f; mx[h]=NEG; dg[h]=0.f; }
        }
    }

    // last CTA finalizes
    __shared__ int sIsLast;
    if (tid == 0) {
        __threadfence();
        unsigned long long old = atomicAdd(&g_done, 1ull);
        sIsLast = (int)(((old + 1ull) % NCTA) == 0ull);
    }
    __syncthreads();
    if (sIsLast) {
        __threadfence();
        double* sm = (double*)(smem + SM_ST);
        double sloc = 0.0;
        for (int i = tid; i < BB; i += 512) {
            float s = g_psum[i];
            float m = funmap(g_pmaxu[i]);
            float total = s + __expf((m - 1.0f) * INVT);
            sloc += (double)(INVT * (1.0f - g_diag[i]) + logf(total));
        }
        sm[tid] = sloc;
        __syncthreads();
        for (int st = 256; st > 0; st >>= 1) {
            if (tid < st) sm[tid] += sm[tid + st];
            __syncthreads();
        }
        if (tid == 0) out[0] = (float)(sm[0] / (double)BB);
    }
}

extern "C" void kernel_launch(void* const* d_in, const int* in_sizes, int n_in,
                              void* d_out, int out_size) {
    const float* anchor   = (const float*)d_in[0];
    const float* positive = (const float*)d_in[1];
    cudaFuncSetAttribute(fused_kernel, cudaFuncAttributeMaxDynamicSharedMemorySize, SMEM_BYTES);
    nrm_kernel<<<dim3(BB/64, 2), 512>>>(anchor, positive);
    fused_kernel<<<NCTA, 512, SMEM_BYTES>>>((float*)d_out);
}